// round 6
// baseline (speedup 1.0000x reference)
#include <cuda_runtime.h>
#include <cstdint>

#define NMAX   200704      // >= N=200000, bounds all clamped gathers
#define KNBR   64
#define TPB    128
#define PPB    32          // points per block (4 threads/point)
#define SROW   68          // smem row stride (words) per point
#define QOFF   17          // offset of each 16-neighbor quarter within a row

__device__ float4 g_table[NMAX];
__device__ int    g_is32;   // 1 if neighbor_matrix is actually int32 data

// ---------------------------------------------------------------------------
// pack: build (x,y,z,u) float4 table. Block 0 also classifies the neighbor
// buffer dtype (JAX silently demotes int64->int32 without x64): int32 data
// read as int64 yields values outside [-1, n) with overwhelming probability
// over 2048 samples. Deterministic every replay.
// ---------------------------------------------------------------------------
__global__ void pack_kernel(const float* __restrict__ coords,
                            const float* __restrict__ y,
                            const long long* __restrict__ nb,
                            int nb_elems, int n)
{
    int i = blockIdx.x * blockDim.x + threadIdx.x;
    if (i < n) {
        g_table[i] = make_float4(coords[3 * i + 0],
                                 coords[3 * i + 1],
                                 coords[3 * i + 2],
                                 y[i]);
    }
    if (blockIdx.x == 0) {
        int bad = 0;
        int lim = nb_elems / 2;
        if (lim > 2048) lim = 2048;
        for (int t = threadIdx.x; t < lim; t += blockDim.x) {
            long long v = nb[t];
            if (v < -1 || v >= (long long)n) bad = 1;
        }
        bad = __syncthreads_or(bad);
        if (threadIdx.x == 0) g_is32 = bad;
    }
}

// ---------------------------------------------------------------------------
// deriv: FOUR THREADS per point (32 points / 128-thread block). Each thread
// gathers+accumulates 16 of the point's 64 neighbors; two shfl.bfly rounds
// (xor 1, xor 2) combine the 9 partial sums; lane q==0 solves the 3x3.
// Kernel is L1-wavefront/latency bound: smaller smem (8.7KB) + 56-reg cap
// -> 9 resident blocks (36 warps/SM), grid 6250 -> wave-quantization ~1.07.
// Smem: [32 points][68 words]; thread (p,q) reads words q*17 + m, m=0..15.
// Bank = (4p + 17q + m) mod 32 is bijective over a warp => conflict-free.
// Sum order is permuted vs reference — legal, order-independent to fp noise.
// ---------------------------------------------------------------------------
__global__ __launch_bounds__(TPB, 9)
void deriv_kernel(const void* __restrict__ nb_raw,
                  float* __restrict__ out, int n)
{
    __shared__ int sidx[PPB * SROW];

    const int tid  = threadIdx.x;
    const int base = blockIdx.x * PPB;
    const bool is32 = (g_is32 != 0);

    const int p = tid >> 2;              // local point 0..31
    const int q = tid & 3;               // which 16-neighbor quarter
    const int i = base + p;              // global point (< NMAX by grid bound)

    // ---- stage 32x64 indices, fully coalesced wide loads ----
    if (is32) {
        const int4* __restrict__ nb4 = (const int4*)nb_raw;
        const size_t gbase = (size_t)blockIdx.x * (PPB * KNBR / 4);
        #pragma unroll
        for (int jj = 0; jj < 4; jj++) {
            int l  = tid + jj * TPB;         // 0..511
            int pt = l >> 4;                 // local point
            int c4 = l & 15;                 // which int4 in the row
            int4 v = make_int4(-1, -1, -1, -1);
            if (base + pt < n) v = nb4[gbase + l];
            int qq = c4 >> 2;                // quarter (4 int4 each)
            int mm = (c4 & 3) * 4;           // word within quarter
            int* r = &sidx[pt * SROW + qq * QOFF + mm];
            r[0] = v.x; r[1] = v.y; r[2] = v.z; r[3] = v.w;
        }
    } else {
        const longlong2* __restrict__ nb2 = (const longlong2*)nb_raw;
        const size_t gbase = (size_t)blockIdx.x * (PPB * KNBR / 2);
        #pragma unroll
        for (int jj = 0; jj < 8; jj++) {
            int l  = tid + jj * TPB;         // 0..1023
            int pt = l >> 5;
            int c2 = l & 31;
            longlong2 v = make_longlong2(-1, -1);
            if (base + pt < n) v = nb2[gbase + l];
            int qq = c2 >> 3;                // quarter (8 ll2 each)
            int mm = (c2 & 7) * 2;
            int* r = &sidx[pt * SROW + qq * QOFF + mm];
            r[0] = (int)v.x; r[1] = (int)v.y;
        }
    }
    __syncthreads();

    const float4 c = __ldg(&g_table[i]);

    float axx = 0.f, axy = 0.f, axz = 0.f;
    float ayy = 0.f, ayz = 0.f, azz = 0.f;
    float bx  = 0.f, by  = 0.f, bz  = 0.f;

    const int* __restrict__ row = &sidx[p * SROW + q * QOFF];

    #pragma unroll 8
    for (int k = 0; k < 16; k++) {
        int j = row[k];
        if (j < 0) j = i;                    // masked neighbor -> dv = du = 0
        const float4 t = __ldg(&g_table[j]);

        float dx = t.x - c.x;
        float dy = t.y - c.y;
        float dz = t.z - c.z;
        float du = t.w - c.w;

        float r2 = fmaf(dx, dx, fmaf(dy, dy, fmaf(dz, dz, 1e-8f)));
        float w;
        asm("rcp.approx.f32 %0, %1;" : "=f"(w) : "f"(r2));

        float wdx = w * dx, wdy = w * dy, wdz = w * dz;
        axx = fmaf(wdx, dx, axx);
        axy = fmaf(wdx, dy, axy);
        axz = fmaf(wdx, dz, axz);
        ayy = fmaf(wdy, dy, ayy);
        ayz = fmaf(wdy, dz, ayz);
        azz = fmaf(wdz, dz, azz);
        bx  = fmaf(wdx, du, bx);
        by  = fmaf(wdy, du, by);
        bz  = fmaf(wdz, du, bz);
    }

    // ---- quad reduction across the 4 lanes of each point ----
    const unsigned FULL = 0xffffffffu;
    #pragma unroll
    for (int d = 1; d <= 2; d <<= 1) {
        axx += __shfl_xor_sync(FULL, axx, d);
        axy += __shfl_xor_sync(FULL, axy, d);
        axz += __shfl_xor_sync(FULL, axz, d);
        ayy += __shfl_xor_sync(FULL, ayy, d);
        ayz += __shfl_xor_sync(FULL, ayz, d);
        azz += __shfl_xor_sync(FULL, azz, d);
        bx  += __shfl_xor_sync(FULL, bx , d);
        by  += __shfl_xor_sync(FULL, by , d);
        bz  += __shfl_xor_sync(FULL, bz , d);
    }

    if (q == 0 && i < n) {
        // Tikhonov regularizer
        axx += 1e-6f; ayy += 1e-6f; azz += 1e-6f;

        // Symmetric 3x3 solve via adjugate (Cramer)
        float m00 = fmaf(ayy, azz, -ayz * ayz);
        float m01 = fmaf(axz, ayz, -axy * azz);
        float m02 = fmaf(axy, ayz, -axz * ayy);
        float m11 = fmaf(axx, azz, -axz * axz);
        float m12 = fmaf(axy, axz, -axx * ayz);
        float m22 = fmaf(axx, ayy, -axy * axy);

        float det = fmaf(axx, m00, fmaf(axy, m01, axz * m02));
        float inv;
        asm("rcp.approx.f32 %0, %1;" : "=f"(inv) : "f"(det));

        float gx = fmaf(m00, bx, fmaf(m01, by, m02 * bz)) * inv;
        float gy = fmaf(m01, bx, fmaf(m11, by, m12 * bz)) * inv;
        float gz = fmaf(m02, bx, fmaf(m12, by, m22 * bz)) * inv;

        out[3 * i + 0] = gx;
        out[3 * i + 1] = gy;
        out[3 * i + 2] = gz;
    }
}

// ---------------------------------------------------------------------------
extern "C" void kernel_launch(void* const* d_in, const int* in_sizes, int n_in,
                              void* d_out, int out_size)
{
    const float* coords = (const float*)d_in[0];   // [N, 3] float32
    const void*  nb     = d_in[1];                 // [N, 64] int64 (demoted int32 in practice)
    const float* yv     = (const float*)d_in[2];   // [N, 1] float32
    float*       out    = (float*)d_out;           // [N, 3] float32

    const int n = in_sizes[0] / 3;

    pack_kernel<<<(n + 255) / 256, 256>>>(coords, yv,
                                          (const long long*)nb, in_sizes[1], n);
    deriv_kernel<<<(n + PPB - 1) / PPB, TPB>>>(nb, out, n);
}

// round 7
// speedup vs baseline: 1.0109x; 1.0109x over previous
#include <cuda_runtime.h>
#include <cstdint>

#define NMAX   200704      // >= N=200000, bounds all clamped gathers
#define KNBR   64
#define TPB    128
#define PPB    64          // points per block (2 threads/point)
#define SROW   68          // smem row stride in words (16B-aligned, +4 pad)

__device__ float4 g_table[NMAX];
__device__ int    g_is32;   // 1 if neighbor_matrix is actually int32 data

__device__ __forceinline__ unsigned smem_u32(const void* p) {
    return (unsigned)__cvta_generic_to_shared(p);
}

// ---------------------------------------------------------------------------
// pack: build (x,y,z,u) float4 table. Block 0 also classifies the neighbor
// buffer dtype (JAX silently demotes int64->int32 without x64): int32 data
// read as int64 yields values outside [-1, n) with overwhelming probability
// over 2048 samples. Deterministic every replay.
// ---------------------------------------------------------------------------
__global__ void pack_kernel(const float* __restrict__ coords,
                            const float* __restrict__ y,
                            const long long* __restrict__ nb,
                            int nb_elems, int n)
{
    int i = blockIdx.x * blockDim.x + threadIdx.x;
    if (i < n) {
        g_table[i] = make_float4(coords[3 * i + 0],
                                 coords[3 * i + 1],
                                 coords[3 * i + 2],
                                 y[i]);
    }
    if (blockIdx.x == 0) {
        int bad = 0;
        int lim = nb_elems / 2;
        if (lim > 2048) lim = 2048;
        for (int t = threadIdx.x; t < lim; t += blockDim.x) {
            long long v = nb[t];
            if (v < -1 || v >= (long long)n) bad = 1;
        }
        bad = __syncthreads_or(bad);
        if (threadIdx.x == 0) g_is32 = bad;
    }
}

// ---------------------------------------------------------------------------
// deriv: TWO THREADS per point (64 points / 128-thread block), the proven
// best structure (r5). Each thread gathers+accumulates 32 of the point's 64
// neighbors; one shfl.bfly(1) combines the 9 partial sums; even lane solves.
// This round: cp.async index staging (no register round-trip, shorter block-
// start bubble) + 56-reg cap for 9 resident blocks (36 warps/SM).
// Smem rows are contiguous (stride 68 words); the 2-way LDS bank conflict
// this creates costs ~1 extra cyc per warp-LDS — negligible vs 12.8M gather
// wavefronts. Sum order matches gather order per thread; order-independent.
// ---------------------------------------------------------------------------
__global__ __launch_bounds__(TPB, 9)
void deriv_kernel(const void* __restrict__ nb_raw,
                  float* __restrict__ out, int n)
{
    __shared__ int sidx[PPB * SROW];

    const int tid  = threadIdx.x;
    const int base = blockIdx.x * PPB;
    const bool is32 = (g_is32 != 0);

    const int p    = tid >> 1;           // local point 0..63
    const int half = tid & 1;            // which 32 neighbors
    const int i    = base + p;           // global point (< NMAX by grid bound)

    // ---- stage 64x64 indices ----
    if (is32 && base + PPB <= n) {
        // Hot path: cp.async 16B chunks, fully coalesced, no reg round-trip.
        const int4* __restrict__ nb4 = (const int4*)nb_raw;
        const size_t gbase = (size_t)blockIdx.x * (PPB * KNBR / 4);
        #pragma unroll
        for (int jj = 0; jj < 8; jj++) {
            int l  = tid + jj * TPB;         // 0..1023 int4 chunks
            int pt = l >> 4;                 // local point
            int c4 = l & 15;                 // which int4 in the row
            unsigned dst = smem_u32(&sidx[pt * SROW + c4 * 4]);
            const int4* src = &nb4[gbase + l];
            asm volatile("cp.async.cg.shared.global [%0], [%1], 16;"
                         :: "r"(dst), "l"(src));
        }
        asm volatile("cp.async.commit_group;");
        asm volatile("cp.async.wait_group 0;");
    } else if (is32) {
        const int* __restrict__ nb32 = (const int*)nb_raw;
        for (int l = tid; l < PPB * KNBR; l += TPB) {
            int pt = l >> 6, k = l & 63;
            int gp = base + pt;
            sidx[pt * SROW + k] = (gp < n) ? nb32[(size_t)gp * KNBR + k] : -1;
        }
    } else {
        const longlong2* __restrict__ nb2 = (const longlong2*)nb_raw;
        const size_t gbase = (size_t)blockIdx.x * (PPB * KNBR / 2);
        #pragma unroll
        for (int jj = 0; jj < 16; jj++) {
            int l  = tid + jj * TPB;         // 0..2047 ll2 chunks
            int pt = l >> 5;
            int c2 = l & 31;
            longlong2 v = make_longlong2(-1, -1);
            if (base + pt < n) v = nb2[gbase + l];
            int* r = &sidx[pt * SROW + c2 * 2];
            r[0] = (int)v.x; r[1] = (int)v.y;
        }
    }
    __syncthreads();

    const float4 c = g_table[i];

    float axx = 0.f, axy = 0.f, axz = 0.f;
    float ayy = 0.f, ayz = 0.f, azz = 0.f;
    float bx  = 0.f, by  = 0.f, bz  = 0.f;

    const int* __restrict__ row = &sidx[p * SROW + half * 32];

    #pragma unroll 8
    for (int k = 0; k < 32; k++) {
        int j = row[k];
        if (j < 0) j = i;                    // masked neighbor -> dv = du = 0
        const float4 t = __ldg(&g_table[j]);

        float dx = t.x - c.x;
        float dy = t.y - c.y;
        float dz = t.z - c.z;
        float du = t.w - c.w;

        float r2 = fmaf(dx, dx, fmaf(dy, dy, fmaf(dz, dz, 1e-8f)));
        float w;
        asm("rcp.approx.f32 %0, %1;" : "=f"(w) : "f"(r2));

        float wdx = w * dx, wdy = w * dy, wdz = w * dz;
        axx = fmaf(wdx, dx, axx);
        axy = fmaf(wdx, dy, axy);
        axz = fmaf(wdx, dz, axz);
        ayy = fmaf(wdy, dy, ayy);
        ayz = fmaf(wdy, dz, ayz);
        azz = fmaf(wdz, dz, azz);
        bx  = fmaf(wdx, du, bx);
        by  = fmaf(wdy, du, by);
        bz  = fmaf(wdz, du, bz);
    }

    // ---- pair reduction: lanes 2a and 2a+1 combine (xor 1) ----
    const unsigned FULL = 0xffffffffu;
    axx += __shfl_xor_sync(FULL, axx, 1);
    axy += __shfl_xor_sync(FULL, axy, 1);
    axz += __shfl_xor_sync(FULL, axz, 1);
    ayy += __shfl_xor_sync(FULL, ayy, 1);
    ayz += __shfl_xor_sync(FULL, ayz, 1);
    azz += __shfl_xor_sync(FULL, azz, 1);
    bx  += __shfl_xor_sync(FULL, bx , 1);
    by  += __shfl_xor_sync(FULL, by , 1);
    bz  += __shfl_xor_sync(FULL, bz , 1);

    if (half == 0 && i < n) {
        // Tikhonov regularizer
        axx += 1e-6f; ayy += 1e-6f; azz += 1e-6f;

        // Symmetric 3x3 solve via adjugate (Cramer)
        float m00 = fmaf(ayy, azz, -ayz * ayz);
        float m01 = fmaf(axz, ayz, -axy * azz);
        float m02 = fmaf(axy, ayz, -axz * ayy);
        float m11 = fmaf(axx, azz, -axz * axz);
        float m12 = fmaf(axy, axz, -axx * ayz);
        float m22 = fmaf(axx, ayy, -axy * axy);

        float det = fmaf(axx, m00, fmaf(axy, m01, axz * m02));
        float inv;
        asm("rcp.approx.f32 %0, %1;" : "=f"(inv) : "f"(det));

        float gx = fmaf(m00, bx, fmaf(m01, by, m02 * bz)) * inv;
        float gy = fmaf(m01, bx, fmaf(m11, by, m12 * bz)) * inv;
        float gz = fmaf(m02, bx, fmaf(m12, by, m22 * bz)) * inv;

        out[3 * i + 0] = gx;
        out[3 * i + 1] = gy;
        out[3 * i + 2] = gz;
    }
}

// ---------------------------------------------------------------------------
extern "C" void kernel_launch(void* const* d_in, const int* in_sizes, int n_in,
                              void* d_out, int out_size)
{
    const float* coords = (const float*)d_in[0];   // [N, 3] float32
    const void*  nb     = d_in[1];                 // [N, 64] int64 (demoted int32 in practice)
    const float* yv     = (const float*)d_in[2];   // [N, 1] float32
    float*       out    = (float*)d_out;           // [N, 3] float32

    const int n = in_sizes[0] / 3;

    pack_kernel<<<(n + 255) / 256, 256>>>(coords, yv,
                                          (const long long*)nb, in_sizes[1], n);
    deriv_kernel<<<(n + PPB - 1) / PPB, TPB>>>(nb, out, n);
}

// round 9
// speedup vs baseline: 1.0143x; 1.0034x over previous
#include <cuda_runtime.h>
#include <cstdint>

#define NMAX   200704      // >= N=200000, bounds all clamped gathers
#define KNBR   64
#define TPB    128
#define PPB    64          // points per block (2 threads/point)
#define SROW   66          // words per point row (two 33-word half-regions)
#define HOFF   33          // half-region offset -> conflict-free banks

__device__ float4 g_table[NMAX];
__device__ int    g_is32;   // 1 if neighbor_matrix is actually int32 data

__device__ __forceinline__ unsigned smem_u32(const void* p) {
    return (unsigned)__cvta_generic_to_shared(p);
}

// ---------------------------------------------------------------------------
// pack: build (x,y,z,u) float4 table. Block 0 also classifies the neighbor
// buffer dtype (JAX silently demotes int64->int32 without x64): int32 data
// read as int64 yields values outside [-1, n) with overwhelming probability
// over 2048 samples. Deterministic every replay.
// ---------------------------------------------------------------------------
__global__ void pack_kernel(const float* __restrict__ coords,
                            const float* __restrict__ y,
                            const long long* __restrict__ nb,
                            int nb_elems, int n)
{
    int i = blockIdx.x * blockDim.x + threadIdx.x;
    if (i < n) {
        g_table[i] = make_float4(coords[3 * i + 0],
                                 coords[3 * i + 1],
                                 coords[3 * i + 2],
                                 y[i]);
    }
    if (blockIdx.x == 0) {
        int bad = 0;
        int lim = nb_elems / 2;
        if (lim > 2048) lim = 2048;
        for (int t = threadIdx.x; t < lim; t += blockDim.x) {
            long long v = nb[t];
            if (v < -1 || v >= (long long)n) bad = 1;
        }
        bad = __syncthreads_or(bad);
        if (threadIdx.x == 0) g_is32 = bad;
    }
}

// ---------------------------------------------------------------------------
// deriv: r5 structure (2 threads/point, 64 points/block, 8 resident blocks,
// SROW=66 conflict-free smem) + correctly-aligned cp.async double buffering.
// Layout: col k of point p lives at word p*66 + (k>=32)*33 + (k&31).
// Staging: two cp.async.ca 4-byte commit groups (cols [0,32), [32,64)).
//   Each warp-iteration stages one 32-col row-half: global side = 32
//   consecutive ints (one 128B wavefront), smem side = 32 consecutive words
//   from an arbitrary base (conflict-free). 4B alignment holds for all rows.
// Compute: thread (p,h) consumes cols {2m+h} then {32+2m+h}, m=0..15.
//   LDS bank = (2p + 2m + h [+1]) mod 32 -> bijective per warp.
//   wait_group 1 gates chunk0; chunk1 DRAM latency hides behind 16 gathers.
// Sum order is a permutation of the reference -> fp-noise only.
// ---------------------------------------------------------------------------
__global__ __launch_bounds__(TPB, 8)
void deriv_kernel(const void* __restrict__ nb_raw,
                  float* __restrict__ out, int n)
{
    __shared__ int sidx[PPB * SROW];

    const int tid  = threadIdx.x;
    const int base = blockIdx.x * PPB;
    const bool is32 = (g_is32 != 0);

    const int p = tid >> 1;              // local point 0..63
    const int h = tid & 1;               // parity within the point
    const int i = base + p;              // global point (grid*PPB == 200000 <= NMAX)

    const bool hot = is32 && (base + PPB <= n);

    // ---- stage indices ----
    if (hot) {
        const int* __restrict__ nb32 = (const int*)nb_raw;
        const size_t gbase = (size_t)base * KNBR;
        #pragma unroll
        for (int c = 0; c < 2; c++) {
            #pragma unroll
            for (int jj = 0; jj < 16; jj++) {
                int l  = tid + jj * TPB;       // 0..2047
                int pt = l >> 5;               // local point
                int k  = l & 31;               // col within this chunk
                unsigned dst = smem_u32(&sidx[pt * SROW + c * HOFF + k]);
                const int* src = &nb32[gbase + (size_t)pt * KNBR + c * 32 + k];
                asm volatile("cp.async.ca.shared.global [%0], [%1], 4;"
                             :: "r"(dst), "l"(src));
            }
            asm volatile("cp.async.commit_group;");
        }
        asm volatile("cp.async.wait_group 1;");    // chunk 0 landed
    } else if (is32) {
        const int* __restrict__ nb32 = (const int*)nb_raw;
        for (int l = tid; l < PPB * KNBR; l += TPB) {
            int pt = l >> 6, k = l & 63;
            int gp = base + pt;
            int v  = (gp < n) ? nb32[(size_t)gp * KNBR + k] : -1;
            sidx[pt * SROW + (k >> 5) * HOFF + (k & 31)] = v;
        }
    } else {
        const longlong2* __restrict__ nb2 = (const longlong2*)nb_raw;
        const size_t gbase = (size_t)blockIdx.x * (PPB * KNBR / 2);
        #pragma unroll
        for (int jj = 0; jj < 16; jj++) {
            int l  = tid + jj * TPB;           // 0..2047 ll2 chunks
            int pt = l >> 5;
            int c2 = l & 31;                   // cols 2*c2, 2*c2+1
            longlong2 v = make_longlong2(-1, -1);
            if (base + pt < n) v = nb2[gbase + l];
            int k0 = 2 * c2;
            int* r = &sidx[pt * SROW + (k0 >> 5) * HOFF + (k0 & 31)];
            r[0] = (int)v.x; r[1] = (int)v.y;
        }
    }
    __syncthreads();

    const float4 c = g_table[i];

    float axx = 0.f, axy = 0.f, axz = 0.f;
    float ayy = 0.f, ayz = 0.f, azz = 0.f;
    float bx  = 0.f, by  = 0.f, bz  = 0.f;

    const int* __restrict__ row0 = &sidx[p * SROW + h];          // chunk0, cols 2m+h
    const int* __restrict__ row1 = row0 + HOFF;                  // chunk1

    // ---- chunk 0 ----
    #pragma unroll 8
    for (int m = 0; m < 16; m++) {
        int j = row0[2 * m];
        if (j < 0) j = i;                    // masked neighbor -> dv = du = 0
        const float4 t = __ldg(&g_table[j]);

        float dx = t.x - c.x;
        float dy = t.y - c.y;
        float dz = t.z - c.z;
        float du = t.w - c.w;

        float r2 = fmaf(dx, dx, fmaf(dy, dy, fmaf(dz, dz, 1e-8f)));
        float w;
        asm("rcp.approx.f32 %0, %1;" : "=f"(w) : "f"(r2));

        float wdx = w * dx, wdy = w * dy, wdz = w * dz;
        axx = fmaf(wdx, dx, axx);
        axy = fmaf(wdx, dy, axy);
        axz = fmaf(wdx, dz, axz);
        ayy = fmaf(wdy, dy, ayy);
        ayz = fmaf(wdy, dz, ayz);
        azz = fmaf(wdz, dz, azz);
        bx  = fmaf(wdx, du, bx);
        by  = fmaf(wdy, du, by);
        bz  = fmaf(wdz, du, bz);
    }

    // ---- gate chunk 1 (staged by all threads of the block) ----
    if (hot) asm volatile("cp.async.wait_group 0;");
    __syncthreads();

    // ---- chunk 1 ----
    #pragma unroll 8
    for (int m = 0; m < 16; m++) {
        int j = row1[2 * m];
        if (j < 0) j = i;
        const float4 t = __ldg(&g_table[j]);

        float dx = t.x - c.x;
        float dy = t.y - c.y;
        float dz = t.z - c.z;
        float du = t.w - c.w;

        float r2 = fmaf(dx, dx, fmaf(dy, dy, fmaf(dz, dz, 1e-8f)));
        float w;
        asm("rcp.approx.f32 %0, %1;" : "=f"(w) : "f"(r2));

        float wdx = w * dx, wdy = w * dy, wdz = w * dz;
        axx = fmaf(wdx, dx, axx);
        axy = fmaf(wdx, dy, axy);
        axz = fmaf(wdx, dz, axz);
        ayy = fmaf(wdy, dy, ayy);
        ayz = fmaf(wdy, dz, ayz);
        azz = fmaf(wdz, dz, azz);
        bx  = fmaf(wdx, du, bx);
        by  = fmaf(wdy, du, by);
        bz  = fmaf(wdz, du, bz);
    }

    // ---- pair reduction: lanes 2a and 2a+1 combine (xor 1) ----
    const unsigned FULL = 0xffffffffu;
    axx += __shfl_xor_sync(FULL, axx, 1);
    axy += __shfl_xor_sync(FULL, axy, 1);
    axz += __shfl_xor_sync(FULL, axz, 1);
    ayy += __shfl_xor_sync(FULL, ayy, 1);
    ayz += __shfl_xor_sync(FULL, ayz, 1);
    azz += __shfl_xor_sync(FULL, azz, 1);
    bx  += __shfl_xor_sync(FULL, bx , 1);
    by  += __shfl_xor_sync(FULL, by , 1);
    bz  += __shfl_xor_sync(FULL, bz , 1);

    if (h == 0 && i < n) {
        // Tikhonov regularizer
        axx += 1e-6f; ayy += 1e-6f; azz += 1e-6f;

        // Symmetric 3x3 solve via adjugate (Cramer)
        float m00 = fmaf(ayy, azz, -ayz * ayz);
        float m01 = fmaf(axz, ayz, -axy * azz);
        float m02 = fmaf(axy, ayz, -axz * ayy);
        float m11 = fmaf(axx, azz, -axz * axz);
        float m12 = fmaf(axy, axz, -axx * ayz);
        float m22 = fmaf(axx, ayy, -axy * axy);

        float det = fmaf(axx, m00, fmaf(axy, m01, axz * m02));
        float inv;
        asm("rcp.approx.f32 %0, %1;" : "=f"(inv) : "f"(det));

        float gx = fmaf(m00, bx, fmaf(m01, by, m02 * bz)) * inv;
        float gy = fmaf(m01, bx, fmaf(m11, by, m12 * bz)) * inv;
        float gz = fmaf(m02, bx, fmaf(m12, by, m22 * bz)) * inv;

        out[3 * i + 0] = gx;
        out[3 * i + 1] = gy;
        out[3 * i + 2] = gz;
    }
}

// ---------------------------------------------------------------------------
extern "C" void kernel_launch(void* const* d_in, const int* in_sizes, int n_in,
                              void* d_out, int out_size)
{
    const float* coords = (const float*)d_in[0];   // [N, 3] float32
    const void*  nb     = d_in[1];                 // [N, 64] int64 (demoted int32 in practice)
    const float* yv     = (const float*)d_in[2];   // [N, 1] float32
    float*       out    = (float*)d_out;           // [N, 3] float32

    const int n = in_sizes[0] / 3;

    pack_kernel<<<(n + 255) / 256, 256>>>(coords, yv,
                                          (const long long*)nb, in_sizes[1], n);
    deriv_kernel<<<(n + PPB - 1) / PPB, TPB>>>(nb, out, n);
}

// round 12
// speedup vs baseline: 1.0474x; 1.0326x over previous
#include <cuda_runtime.h>
#include <cstdint>

#define NMAX   200704      // >= N=200000, bounds all clamped gathers
#define KNBR   64
#define TPB    128
#define PPB    64          // points per block (2 threads/point)
#define SROW   66          // smem row stride (words) per point
#define HOFF   33          // offset of second half within a row

__device__ float4 g_table[NMAX];
__device__ int    g_is32;   // 1 if neighbor_matrix is actually int32 data

// ---------------------------------------------------------------------------
// pack: build (x,y,z,u) float4 table. Block 0 also classifies the neighbor
// buffer dtype (JAX silently demotes int64->int32 without x64): int32 data
// read as int64 yields values outside [-1, n) with overwhelming probability
// over 2048 samples. Deterministic every replay.
// ---------------------------------------------------------------------------
__global__ void pack_kernel(const float* __restrict__ coords,
                            const float* __restrict__ y,
                            const long long* __restrict__ nb,
                            int nb_elems, int n)
{
    int i = blockIdx.x * blockDim.x + threadIdx.x;
    if (i < n) {
        g_table[i] = make_float4(coords[3 * i + 0],
                                 coords[3 * i + 1],
                                 coords[3 * i + 2],
                                 y[i]);
    }
    if (blockIdx.x == 0) {
        int bad = 0;
        int lim = nb_elems / 2;
        if (lim > 2048) lim = 2048;
        for (int t = threadIdx.x; t < lim; t += blockDim.x) {
            long long v = nb[t];
            if (v < -1 || v >= (long long)n) bad = 1;
        }
        bad = __syncthreads_or(bad);
        if (threadIdx.x == 0) g_is32 = bad;
    }
}

// ---------------------------------------------------------------------------
// deriv: TWO THREADS per point (64 points / 128-thread block) — the r5
// structure, which beat every occupancy/cp.async variant tried (r6-r9).
// Each thread gathers+accumulates 32 of the point's 64 neighbors; one
// shfl.bfly(1) combines the 9 partial sums; BOTH lanes then hold the full
// sums — even lane solves+stores x,y, odd lane solves+stores z (cheap, and
// removes one strided STG from the critical lane).
// Smem: [64 points][66 words]; thread (p,h) reads words h*33 + m, m=0..31.
// Bank = (2p + h + m) mod 32 -> bijective over a warp => conflict-free.
// Center-point load is hoisted above staging to overlap its L2 latency.
// ---------------------------------------------------------------------------
__global__ __launch_bounds__(TPB, 8)
void deriv_kernel(const void* __restrict__ nb_raw,
                  float* __restrict__ out, int n)
{
    __shared__ int sidx[PPB * SROW];

    const int tid  = threadIdx.x;
    const int base = blockIdx.x * PPB;
    const bool is32 = (g_is32 != 0);

    const int p    = tid >> 1;           // local point 0..63
    const int half = tid & 1;            // which 32 neighbors
    const int i    = base + p;           // global point (< NMAX by grid bound)

    // Hoisted: overlap center load latency with index staging.
    const float4 c = g_table[i];

    // ---- stage 64x64 indices, fully coalesced wide loads ----
    if (is32) {
        const int4* __restrict__ nb4 = (const int4*)nb_raw;
        const size_t gbase = (size_t)blockIdx.x * (PPB * KNBR / 4);
        #pragma unroll
        for (int jj = 0; jj < 8; jj++) {
            int l  = tid + jj * TPB;         // 0..1023
            int pt = l >> 4;                 // local point
            int c4 = l & 15;                 // which int4 in the row
            int4 v = make_int4(-1, -1, -1, -1);
            if (base + pt < n) v = nb4[gbase + l];
            int hh = c4 >> 3;                // half
            int mm = (c4 & 7) * 4;           // word within half
            int* r = &sidx[pt * SROW + hh * HOFF + mm];
            r[0] = v.x; r[1] = v.y; r[2] = v.z; r[3] = v.w;
        }
    } else {
        const longlong2* __restrict__ nb2 = (const longlong2*)nb_raw;
        const size_t gbase = (size_t)blockIdx.x * (PPB * KNBR / 2);
        #pragma unroll
        for (int jj = 0; jj < 16; jj++) {
            int l  = tid + jj * TPB;         // 0..2047
            int pt = l >> 5;
            int c2 = l & 31;
            longlong2 v = make_longlong2(-1, -1);
            if (base + pt < n) v = nb2[gbase + l];
            int hh = c2 >> 4;
            int mm = (c2 & 15) * 2;
            int* r = &sidx[pt * SROW + hh * HOFF + mm];
            r[0] = (int)v.x; r[1] = (int)v.y;
        }
    }
    __syncthreads();

    float axx = 0.f, axy = 0.f, axz = 0.f;
    float ayy = 0.f, ayz = 0.f, azz = 0.f;
    float bx  = 0.f, by  = 0.f, bz  = 0.f;

    const int* __restrict__ row = &sidx[p * SROW + half * HOFF];

    #pragma unroll 8
    for (int k = 0; k < 32; k++) {
        int j = row[k];
        if (j < 0) j = i;                    // masked neighbor -> dv = du = 0
        const float4 t = __ldg(&g_table[j]);

        float dx = t.x - c.x;
        float dy = t.y - c.y;
        float dz = t.z - c.z;
        float du = t.w - c.w;

        float r2 = fmaf(dx, dx, fmaf(dy, dy, fmaf(dz, dz, 1e-8f)));
        float w;
        asm("rcp.approx.f32 %0, %1;" : "=f"(w) : "f"(r2));

        float wdx = w * dx, wdy = w * dy, wdz = w * dz;
        axx = fmaf(wdx, dx, axx);
        axy = fmaf(wdx, dy, axy);
        axz = fmaf(wdx, dz, axz);
        ayy = fmaf(wdy, dy, ayy);
        ayz = fmaf(wdy, dz, ayz);
        azz = fmaf(wdz, dz, azz);
        bx  = fmaf(wdx, du, bx);
        by  = fmaf(wdy, du, by);
        bz  = fmaf(wdz, du, bz);
    }

    // ---- pair reduction: lanes 2a and 2a+1 combine (xor 1) ----
    // After this, BOTH lanes hold the complete sums.
    const unsigned FULL = 0xffffffffu;
    axx += __shfl_xor_sync(FULL, axx, 1);
    axy += __shfl_xor_sync(FULL, axy, 1);
    axz += __shfl_xor_sync(FULL, axz, 1);
    ayy += __shfl_xor_sync(FULL, ayy, 1);
    ayz += __shfl_xor_sync(FULL, ayz, 1);
    azz += __shfl_xor_sync(FULL, azz, 1);
    bx  += __shfl_xor_sync(FULL, bx , 1);
    by  += __shfl_xor_sync(FULL, by , 1);
    bz  += __shfl_xor_sync(FULL, bz , 1);

    if (i < n) {
        // Tikhonov regularizer
        axx += 1e-6f; ayy += 1e-6f; azz += 1e-6f;

        // Symmetric 3x3 solve via adjugate (Cramer) — both lanes compute
        // (identical inputs -> identical results); each stores its share.
        float m00 = fmaf(ayy, azz, -ayz * ayz);
        float m01 = fmaf(axz, ayz, -axy * azz);
        float m02 = fmaf(axy, ayz, -axz * ayy);
        float m11 = fmaf(axx, azz, -axz * axz);
        float m12 = fmaf(axy, axz, -axx * ayz);
        float m22 = fmaf(axx, ayy, -axy * axy);

        float det = fmaf(axx, m00, fmaf(axy, m01, axz * m02));
        float inv;
        asm("rcp.approx.f32 %0, %1;" : "=f"(inv) : "f"(det));

        if (half == 0) {
            float gx = fmaf(m00, bx, fmaf(m01, by, m02 * bz)) * inv;
            float gy = fmaf(m01, bx, fmaf(m11, by, m12 * bz)) * inv;
            out[3 * i + 0] = gx;
            out[3 * i + 1] = gy;
        } else {
            float gz = fmaf(m02, bx, fmaf(m12, by, m22 * bz)) * inv;
            out[3 * i + 2] = gz;
        }
    }
}

// ---------------------------------------------------------------------------
extern "C" void kernel_launch(void* const* d_in, const int* in_sizes, int n_in,
                              void* d_out, int out_size)
{
    const float* coords = (const float*)d_in[0];   // [N, 3] float32
    const void*  nb     = d_in[1];                 // [N, 64] int64 (demoted int32 in practice)
    const float* yv     = (const float*)d_in[2];   // [N, 1] float32
    float*       out    = (float*)d_out;           // [N, 3] float32

    const int n = in_sizes[0] / 3;

    pack_kernel<<<(n + 255) / 256, 256>>>(coords, yv,
                                          (const long long*)nb, in_sizes[1], n);
    deriv_kernel<<<(n + PPB - 1) / PPB, TPB>>>(nb, out, n);
}